// round 13
// baseline (speedup 1.0000x reference)
#include <cuda_runtime.h>
#include <math.h>
#include <stdint.h>

// Problem constants (B=2, S=2048, D=1024, H=16, Dk=64)
#define BB 2
#define SS 2048
#define DD 1024
#define HH 16
#define DK 64
#define BH (BB*HH)

#define QSCALE (0.125f * 1.44269504088896340736f)
#define PADL 72   // k_lsum/k_wsum: 64-float rows + 8 pad (LDS.64 conflict-free)
#define PADP 36   // k_proj: 32-float rows + 4 pad

__device__ __forceinline__ uint32_t smaddr(const void* p) {
    return (uint32_t)__cvta_generic_to_shared(p);
}
__device__ __forceinline__ void cpa16(uint32_t dst, const void* src) {
    asm volatile("cp.async.cg.shared.global [%0], [%1], 16;" :: "r"(dst), "l"(src));
}
__device__ __forceinline__ void cpa16z(uint32_t dst, const void* src) {
    asm volatile("cp.async.cg.shared.global [%0], [%1], 16, 0;" :: "r"(dst), "l"(src));
}
#define CP_COMMIT() asm volatile("cp.async.commit_group;")
#define CP_WAIT0()  asm volatile("cp.async.wait_group 0;")
#define CP_WAIT1()  asm volatile("cp.async.wait_group 1;")

__device__ __forceinline__ uint32_t f2tf(float x) {
    uint32_t r; asm("cvt.rna.tf32.f32 %0, %1;" : "=r"(r) : "f"(x)); return r;
}
__device__ __forceinline__ uint32_t rna_bits(uint32_t u) {
    return f2tf(__uint_as_float(u));
}
__device__ __forceinline__ void mma8(float* d, const uint32_t* a, uint32_t b0, uint32_t b1) {
    asm("mma.sync.aligned.m16n8k8.row.col.f32.tf32.tf32.f32 "
        "{%0,%1,%2,%3}, {%4,%5,%6,%7}, {%8,%9}, {%0,%1,%2,%3};"
        : "+f"(d[0]), "+f"(d[1]), "+f"(d[2]), "+f"(d[3])
        : "r"(a[0]), "r"(a[1]), "r"(a[2]), "r"(a[3]), "r"(b0), "r"(b1));
}

// ---- static device scratch ----
__device__ float g_Qh[BH*SS*DK];     // tf32-exact values
__device__ float g_Kh[BH*SS*DK];     // tf32-exact values
__device__ float g_WT[2*DD*DD];      // transposed + tf32-rounded Wq, Wk
__device__ float g_lb[BH*SS];
__device__ float g_w [BH*SS];
__device__ float g_ypart[16*BB*HH*DD];
__device__ float g_y [BB*HH*DD];
__device__ float g_cs[BB*DD];
__device__ float g_csp[64*DD];
__device__ float g_outp[64*DD];
__device__ int   g_qidx[BB*SS];
__device__ int   g_cnt [BB];
__device__ float g_cntf[BB];

// ---------------------------------------------------------------------------
// Kernel 0: deterministic mask compaction
// ---------------------------------------------------------------------------
__global__ void k_compact(const int* __restrict__ mask) {
    int b = blockIdx.x;
    int tid = threadIdx.x;
    __shared__ int cnts[256];
    __shared__ int offs[256];
    int base = tid * 8;
    int loc[8];
    int c = 0;
#pragma unroll
    for (int i = 0; i < 8; i++) { loc[i] = mask[b*SS + base + i]; c += (loc[i] != 0); }
    cnts[tid] = c;
    __syncthreads();
    if (tid == 0) {
        int run = 0;
        for (int i = 0; i < 256; i++) { offs[i] = run; run += cnts[i]; }
        g_cnt[b] = run;
        g_cntf[b] = (float)run;
    }
    __syncthreads();
    int o = offs[tid];
#pragma unroll
    for (int i = 0; i < 8; i++) {
        if (loc[i] != 0) { g_qidx[b*SS + o] = base + i; o++; }
    }
}

// ---------------------------------------------------------------------------
// Kernel 0b: transpose + tf32-round W -> g_WT[z]   grid (32,32,2)
// ---------------------------------------------------------------------------
__global__ void k_wtrans(const float* __restrict__ Wq, const float* __restrict__ Wk) {
    __shared__ float t[32][33];
    int sel = blockIdx.z;
    const float* Wsrc = sel ? Wk : Wq;
    float* Wdst = g_WT + (size_t)sel * DD * DD;
    int bx = blockIdx.x * 32, by = blockIdx.y * 32;
    int x = threadIdx.x & 31, y4 = (threadIdx.x >> 5) * 4;
#pragma unroll
    for (int i = 0; i < 4; i++)
        t[y4 + i][x] = Wsrc[(size_t)(by + y4 + i) * DD + bx + x];
    __syncthreads();
#pragma unroll
    for (int i = 0; i < 4; i++)
        Wdst[(size_t)(bx + y4 + i) * DD + by + x] =
            __uint_as_float(f2tf(t[x][y4 + i]));
}

// ---------------------------------------------------------------------------
// Kernel 1: both projection GEMMs in one launch (z = 0:Q, 1:K).   [R10 version]
// Block 128m x 128n, k-chunk 32, 2-stage cp.async. dyn smem 73728 B (3 CTA/SM).
// ---------------------------------------------------------------------------
__global__ __launch_bounds__(256) void k_proj(
    const float* __restrict__ Xq, const float* __restrict__ Xk,
    const float* __restrict__ bq, const float* __restrict__ bk)
{
    extern __shared__ __align__(16) uint32_t smu[];
    int which = blockIdx.z;
    const float* X    = which ? Xk : Xq;
    const float* Wt   = g_WT + (size_t)which * DD * DD;
    const float* bias = which ? bk : bq;
    float scale = which ? 1.0f : QSCALE;
    float* Out = which ? g_Kh : g_Qh;

    int tid = threadIdx.x;
    int w = tid >> 5, lane = tid & 31;
    int g = lane >> 2, t = lane & 3;
    int m0 = blockIdx.x * 128;
    int n0 = blockIdx.y * 128;

#define STAGE_P(s, k0)                                                           \
    {                                                                            \
        uint32_t* B_ = smu + (s) * 256 * PADP;                                   \
        _Pragma("unroll")                                                        \
        for (int i_ = 0; i_ < 8; i_++) {                                         \
            int idx_ = tid + 256 * i_;                                           \
            int row_ = idx_ >> 3, f4_ = idx_ & 7;                                \
            const float* src_ = (row_ < 128)                                     \
                ? (X  + (size_t)(m0 + row_) * DD + (k0) + f4_*4)                 \
                : (Wt + (size_t)(n0 + row_ - 128) * DD + (k0) + f4_*4);          \
            cpa16(smaddr(B_ + row_*PADP + f4_*4), src_);                         \
        }                                                                        \
    }

    float Dp[16][4];
#pragma unroll
    for (int nc = 0; nc < 16; nc++)
#pragma unroll
        for (int j = 0; j < 4; j++) Dp[nc][j] = 0.f;

    STAGE_P(0, 0); CP_COMMIT();
    for (int kt = 0; kt < 32; kt++) {
        if (kt < 31) { STAGE_P((kt + 1) & 1, (kt + 1) * 32); CP_COMMIT(); }
        if (kt < 31) { CP_WAIT1(); } else { CP_WAIT0(); }
        __syncthreads();
        uint32_t* Xs = smu + (kt & 1) * 256 * PADP;
        uint32_t* Ws = Xs + 128 * PADP;
        uint32_t A[4][4];
#pragma unroll
        for (int kc = 0; kc < 4; kc++) {
            int r0 = (w*16 + g)*PADP + t + 8*kc;
            A[kc][0] = rna_bits(Xs[r0]);
            A[kc][1] = rna_bits(Xs[r0 + 8*PADP]);
            A[kc][2] = rna_bits(Xs[r0 + 4]);
            A[kc][3] = rna_bits(Xs[r0 + 8*PADP + 4]);
        }
#pragma unroll
        for (int nc = 0; nc < 16; nc++) {
            int nb = (nc*8 + g)*PADP + t;
#pragma unroll
            for (int kc = 0; kc < 4; kc++)
                mma8(Dp[nc], A[kc], Ws[nb + 8*kc], Ws[nb + 8*kc + 4]);
        }
        __syncthreads();
    }
    int row0 = m0 + w*16 + g;
#pragma unroll
    for (int nc = 0; nc < 16; nc++) {
        int col = n0 + nc*8 + 2*t;
        float bx = bias[col], by = bias[col+1];
        int h = col >> 6, dd = col & 63;
        {
            int b_ = row0 >> 11, s = row0 & 2047;
            float2 o = make_float2(
                __uint_as_float(f2tf((Dp[nc][0] + bx) * scale)),
                __uint_as_float(f2tf((Dp[nc][1] + by) * scale)));
            *(float2*)(Out + (((size_t)(b_*HH + h) * SS + s) << 6) + dd) = o;
        }
        {
            int row1 = row0 + 8;
            int b_ = row1 >> 11, s = row1 & 2047;
            float2 o = make_float2(
                __uint_as_float(f2tf((Dp[nc][2] + bx) * scale)),
                __uint_as_float(f2tf((Dp[nc][3] + by) * scale)));
            *(float2*)(Out + (((size_t)(b_*HH + h) * SS + s) << 6) + dd) = o;
        }
    }
#undef STAGE_P
}

// ---------------------------------------------------------------------------
// Kernel 2 (pass A): lb[q] via tf32 mma; LDS.64 frags.   [R12 version, proven]
// dyn smem 110592 B (2 CTA/SM).
// ---------------------------------------------------------------------------
__global__ __launch_bounds__(256) void k_lsum() {
    extern __shared__ __align__(16) uint32_t smu[];
    uint32_t* Qs = smu;

    int qt = blockIdx.x, bh = blockIdx.y;
    int b = bh >> 4;
    int cnt = g_cnt[b];
    if (qt * 128 >= cnt) return;
    int tid = threadIdx.x;
    int w = tid >> 5, lane = tid & 31;
    int g = lane >> 2, t = lane & 3;
    const float* Qbase = g_Qh + (size_t)bh * SS * 64;
    const float* Kbase = g_Kh + (size_t)bh * SS * 64;

#pragma unroll
    for (int i = 0; i < 8; i++) {
        int idx = tid + 256 * i;
        int row = idx >> 4, d4 = idx & 15;
        int ci = qt*128 + row;
        uint32_t dst = smaddr(Qs + row*PADL + d4*4);
        if (ci < cnt) {
            int s = g_qidx[b*SS + ci];
            cpa16(dst, Qbase + ((size_t)s << 6) + d4*4);
        } else {
            cpa16z(dst, Qbase);
        }
    }
    CP_COMMIT();

#define STAGE_K(kt, s)                                                           \
    {                                                                            \
        uint32_t* Kb_ = smu + 128*PADL + (s) * 128 * PADL;                       \
        _Pragma("unroll")                                                        \
        for (int i_ = 0; i_ < 8; i_++) {                                         \
            int idx_ = tid + 256 * i_;                                           \
            int row_ = idx_ >> 4, d4_ = idx_ & 15;                               \
            cpa16(smaddr(Kb_ + row_*PADL + d4_*4),                               \
                  Kbase + ((size_t)((kt)*128 + row_) << 6) + d4_*4);             \
        }                                                                        \
    }

    STAGE_K(0, 0); CP_COMMIT();
    CP_WAIT1();
    __syncthreads();
    uint32_t A[8][4];
#pragma unroll
    for (int kc = 0; kc < 8; kc++) {
        int r0 = (w*16 + g)*PADL + 8*kc + 2*t;
        uint2 pa0 = *(const uint2*)(Qs + r0);
        uint2 pa1 = *(const uint2*)(Qs + r0 + 8*PADL);
        A[kc][0] = pa0.x; A[kc][2] = pa0.y;
        A[kc][1] = pa1.x; A[kc][3] = pa1.y;
    }
    float rs_lo = 0.f, rs_hi = 0.f;
    for (int kt = 0; kt < 16; kt++) {
        if (kt < 15) { STAGE_K(kt + 1, (kt + 1) & 1); CP_COMMIT(); }
        if (kt < 15) { CP_WAIT1(); } else { CP_WAIT0(); }
        __syncthreads();
        uint32_t* Ks = smu + 128*PADL + (kt & 1) * 128 * PADL;
#pragma unroll 4
        for (int nc = 0; nc < 16; nc++) {
            float c[4] = {0.f, 0.f, 0.f, 0.f};
            int nb = (nc*8 + g)*PADL + 2*t;
#pragma unroll
            for (int kc = 0; kc < 8; kc++) {
                uint2 pb = *(const uint2*)(Ks + nb + 8*kc);
                mma8(c, A[kc], pb.x, pb.y);
            }
            rs_lo += exp2f(c[0]) + exp2f(c[1]);
            rs_hi += exp2f(c[2]) + exp2f(c[3]);
        }
        __syncthreads();
    }
    rs_lo += __shfl_xor_sync(0xffffffffu, rs_lo, 1);
    rs_lo += __shfl_xor_sync(0xffffffffu, rs_lo, 2);
    rs_hi += __shfl_xor_sync(0xffffffffu, rs_hi, 1);
    rs_hi += __shfl_xor_sync(0xffffffffu, rs_hi, 2);
    if (t == 0) {
        int ci = qt*128 + w*16 + g;
        if (ci < cnt)     g_lb[bh*SS + ci]     = log2f(rs_lo);
        if (ci + 8 < cnt) g_lb[bh*SS + ci + 8] = log2f(rs_hi);
    }
#undef STAGE_K
}

// ---------------------------------------------------------------------------
// Kernel 3 (pass B): w[k] via tf32 mma; LDS.64 frags (NEW this round),
// shared-memory wp accumulator (register-light). dyn smem 114688 B (2 CTA/SM).
// ---------------------------------------------------------------------------
__global__ __launch_bounds__(256) void k_wsum() {
    extern __shared__ __align__(16) uint32_t smu[];
    uint32_t* Ks = smu;                         // [128][PADL]
    float* wp = (float*)(smu + 3*128*PADL);     // [8][128]

    int kt = blockIdx.x, bh = blockIdx.y;
    int b = bh >> 4;
    int cnt = g_cnt[b];
    int tid = threadIdx.x;
    int w = tid >> 5, lane = tid & 31;
    int g = lane >> 2, t = lane & 3;
    const float* Qbase = g_Qh + (size_t)bh * SS * 64;
    const float* Kbase = g_Kh + (size_t)bh * SS * 64;
    const float* lbp = g_lb + (size_t)bh * SS;

#pragma unroll
    for (int i = 0; i < 4; i++) wp[tid + 256*i] = 0.f;

#pragma unroll
    for (int i = 0; i < 8; i++) {
        int idx = tid + 256 * i;
        int row = idx >> 4, d4 = idx & 15;
        cpa16(smaddr(Ks + row*PADL + d4*4),
              Kbase + ((size_t)(kt*128 + row) << 6) + d4*4);
    }
    CP_COMMIT();

#define STAGE_QT(qt, s)                                                          \
    {                                                                            \
        uint32_t* Qb_ = smu + 128*PADL + (s) * 128 * PADL;                       \
        _Pragma("unroll")                                                        \
        for (int i_ = 0; i_ < 8; i_++) {                                         \
            int idx_ = tid + 256 * i_;                                           \
            int row_ = idx_ >> 4, d4_ = idx_ & 15;                               \
            int ci_ = (qt)*128 + row_;                                           \
            uint32_t dst_ = smaddr(Qb_ + row_*PADL + d4_*4);                     \
            if (ci_ < cnt) {                                                     \
                int s_ = g_qidx[b*SS + ci_];                                     \
                cpa16(dst_, Qbase + ((size_t)s_ << 6) + d4_*4);                  \
            } else {                                                             \
                cpa16z(dst_, Qbase);                                             \
            }                                                                    \
        }                                                                        \
    }

    int nqt = (cnt + 127) >> 7;
    if (nqt > 0) { STAGE_QT(0, 0); CP_COMMIT(); }

    for (int qt = 0; qt < nqt; qt++) {
        if (qt + 1 < nqt) { STAGE_QT(qt + 1, (qt + 1) & 1); CP_COMMIT(); }
        if (qt + 1 < nqt) { CP_WAIT1(); } else { CP_WAIT0(); }
        __syncthreads();
        uint32_t* Qs = smu + 128*PADL + (qt & 1) * 128 * PADL;
        int ci0 = qt*128 + w*16 + g;
        float lb_lo = (ci0     < cnt) ? lbp[ci0]     : 1e9f;
        float lb_hi = (ci0 + 8 < cnt) ? lbp[ci0 + 8] : 1e9f;
        uint32_t A[8][4];
#pragma unroll
        for (int kc = 0; kc < 8; kc++) {
            int r0 = (w*16 + g)*PADL + 8*kc + 2*t;
            uint2 pa0 = *(const uint2*)(Qs + r0);
            uint2 pa1 = *(const uint2*)(Qs + r0 + 8*PADL);
            A[kc][0] = pa0.x; A[kc][2] = pa0.y;
            A[kc][1] = pa1.x; A[kc][3] = pa1.y;
        }
#pragma unroll 4
        for (int nc = 0; nc < 16; nc++) {
            float c[4] = {0.f, 0.f, 0.f, 0.f};
            int nb = (nc*8 + g)*PADL + 2*t;
#pragma unroll
            for (int kc = 0; kc < 8; kc++) {
                uint2 pb = *(const uint2*)(Ks + nb + 8*kc);
                mma8(c, A[kc], pb.x, pb.y);
            }
            float p0 = exp2f(c[0] - lb_lo) + exp2f(c[2] - lb_hi);
            float p1 = exp2f(c[1] - lb_lo) + exp2f(c[3] - lb_hi);
            p0 += __shfl_xor_sync(0xffffffffu, p0, 4);
            p0 += __shfl_xor_sync(0xffffffffu, p0, 8);
            p0 += __shfl_xor_sync(0xffffffffu, p0, 16);
            p1 += __shfl_xor_sync(0xffffffffu, p1, 4);
            p1 += __shfl_xor_sync(0xffffffffu, p1, 8);
            p1 += __shfl_xor_sync(0xffffffffu, p1, 16);
            if (g == 0) {
                wp[w*128 + nc*8 + 2*t]     += p0;
                wp[w*128 + nc*8 + 2*t + 1] += p1;
            }
        }
        __syncthreads();
    }
    CP_WAIT0();
    __syncthreads();
    if (tid < 128) {
        float wv = 0.f;
#pragma unroll
        for (int i = 0; i < 8; i++) wv += wp[i*128 + tid];
        g_w[bh*SS + kt*128 + tid] = wv;
    }
#undef STAGE_QT
}

// ---------------------------------------------------------------------------
// Kernel 4: y[b,h,j] = sum_k w[b,h,k] * v[b,k,j]     [R10 version]
// ---------------------------------------------------------------------------
__global__ __launch_bounds__(256) void k_ypart(const float* __restrict__ v) {
    int id = blockIdx.x;
    int kt = id & 15;
    int jt = (id >> 4) & 3;
    int b  = id >> 6;
    __shared__ float wsh[16][128];
    int tid = threadIdx.x;
#pragma unroll
    for (int i = 0; i < 8; i++) {
        int idx = tid + 256 * i;
        int h = idx >> 7, kk = idx & 127;
        wsh[h][kk] = g_w[(b*HH + h) * SS + kt*128 + kk];
    }
    __syncthreads();
    int j = jt * 256 + tid;
    float acc[16];
#pragma unroll
    for (int h = 0; h < 16; h++) acc[h] = 0.f;
    const float* vb = v + ((size_t)b * SS + kt*128) * 1024 + j;
    for (int kk = 0; kk < 128; kk++) {
        float vv = vb[(size_t)kk * 1024];
#pragma unroll
        for (int h = 0; h < 16; h++) acc[h] += wsh[h][kk] * vv;
    }
#pragma unroll
    for (int h = 0; h < 16; h++)
        g_ypart[((size_t)(kt*BB + b) * HH + h) * DD + j] = acc[h];
}

__global__ void k_yred() {
    int i = blockIdx.x * 256 + threadIdx.x;
    float s = 0.f;
#pragma unroll
    for (int kt = 0; kt < 16; kt++) s += g_ypart[(size_t)kt * (BB*HH*DD) + i];
    g_y[i] = s;
}

// ---------------------------------------------------------------------------
// Kernel 5: cs[b,c] = sum_j y[b,h(c),j]*Wv[j,c] + cnt_b*bv[c]  (split-j)
// ---------------------------------------------------------------------------
__global__ void k_cs_part(const float* __restrict__ Wv) {
    int bid = blockIdx.x;
    int b = bid >> 5, jc = bid & 31;
    int tid = threadIdx.x;
    int c0 = tid * 4;
    int h = c0 >> 6;
    const float* yrow = g_y + (size_t)(b*HH + h) * DD;
    float4 s = make_float4(0.f, 0.f, 0.f, 0.f);
#pragma unroll 8
    for (int j = jc*32; j < jc*32 + 32; j++) {
        float yv = yrow[j];
        float4 w4 = *(const float4*)(Wv + (size_t)j * 1024 + c0);
        s.x += yv * w4.x; s.y += yv * w4.y; s.z += yv * w4.z; s.w += yv * w4.w;
    }
    *(float4*)(g_csp + (size_t)bid * DD + c0) = s;
}

__global__ void k_cs_red(const float* __restrict__ bv) {
    int idx = blockIdx.x * 256 + threadIdx.x;
    int b = idx >> 10, c = idx & 1023;
    float s = 0.f;
#pragma unroll
    for (int jc = 0; jc < 32; jc++) s += g_csp[(size_t)(b*32 + jc) * DD + c];
    g_cs[idx] = s + g_cntf[b] * bv[c];
}

// ---------------------------------------------------------------------------
// Kernel 6: out[b,d] = sum_c cs[b,c]*Wo[c,d] + cnt_b*bo[d]   (split-c)
// ---------------------------------------------------------------------------
__global__ void k_out_part(const float* __restrict__ Wo) {
    int bid = blockIdx.x;
    int b = bid >> 5, jc = bid & 31;
    int tid = threadIdx.x;
    int d0 = tid * 4;
    const float* cs = g_cs + (size_t)b * 1024;
    float4 s = make_float4(0.f, 0.f, 0.f, 0.f);
#pragma unroll 8
    for (int c = jc*32; c < jc*32 + 32; c++) {
        float cv = cs[c];
        float4 w4 = *(const float4*)(Wo + (size_t)c * 1024 + d0);
        s.x += cv * w4.x; s.y += cv * w4.y; s.z += cv * w4.z; s.w += cv * w4.w;
    }
    *(float4*)(g_outp + (size_t)bid * DD + d0) = s;
}

__global__ void k_out_red(const float* __restrict__ bo, float* __restrict__ out) {
    int idx = blockIdx.x * 256 + threadIdx.x;
    int b = idx >> 10, d = idx & 1023;
    float s = 0.f;
#pragma unroll
    for (int jc = 0; jc < 32; jc++) s += g_outp[(size_t)(b*32 + jc) * DD + d];
    out[idx] = s + g_cntf[b] * bo[d];
}

// ---------------------------------------------------------------------------
extern "C" void kernel_launch(void* const* d_in, const int* in_sizes, int n_in,
                              void* d_out, int out_size) {
    const float* q    = (const float*)d_in[0];
    const float* k    = (const float*)d_in[1];
    const float* v    = (const float*)d_in[2];
    const int*   mask = (const int*)  d_in[3];
    const float* Wq   = (const float*)d_in[4];
    const float* bq   = (const float*)d_in[5];
    const float* Wk   = (const float*)d_in[6];
    const float* bk   = (const float*)d_in[7];
    const float* Wv   = (const float*)d_in[8];
    const float* bv   = (const float*)d_in[9];
    const float* Wo   = (const float*)d_in[10];
    const float* bo   = (const float*)d_in[11];
    float* out = (float*)d_out;

    const int SM_PROJ = 2 * 256 * PADP * 4;             // 73728  (3 CTA/SM)
    const int SM_LSUM = 3 * 128 * PADL * 4;             // 110592 (2 CTA/SM)
    const int SM_WSUM = 3 * 128 * PADL * 4 + 4096;      // 114688 (2 CTA/SM)

    cudaFuncSetAttribute(k_proj, cudaFuncAttributeMaxDynamicSharedMemorySize, SM_PROJ);
    cudaFuncSetAttribute(k_lsum, cudaFuncAttributeMaxDynamicSharedMemorySize, SM_LSUM);
    cudaFuncSetAttribute(k_wsum, cudaFuncAttributeMaxDynamicSharedMemorySize, SM_WSUM);

    k_compact<<<BB, 256>>>(mask);
    k_wtrans<<<dim3(32, 32, 2), 256>>>(Wq, Wk);
    k_proj<<<dim3(32, 8, 2), 256, SM_PROJ>>>(q, k, bq, bk);
    k_lsum<<<dim3(16, 32), 256, SM_LSUM>>>();
    k_wsum<<<dim3(16, 32), 256, SM_WSUM>>>();
    k_ypart<<<128, 256>>>(v);
    k_yred<<<128, 256>>>();
    k_cs_part<<<64, 256>>>(Wv);
    k_cs_red<<<8, 256>>>(bv);
    k_out_part<<<64, 256>>>(Wo);
    k_out_red<<<8, 256>>>(bo, out);
}

// round 14
// speedup vs baseline: 1.0289x; 1.0289x over previous
#include <cuda_runtime.h>
#include <math.h>
#include <stdint.h>

// Problem constants (B=2, S=2048, D=1024, H=16, Dk=64)
#define BB 2
#define SS 2048
#define DD 1024
#define HH 16
#define DK 64
#define BH (BB*HH)

#define QSCALE (0.125f * 1.44269504088896340736f)
#define PADL 72   // k_lsum: 64-float rows + 8 pad (LDS.64 conflict-free)
#define PADW 68   // k_wsum: 64-float rows + 4 pad (scalar frag loads)
#define PADP 36   // k_proj: 32-float rows + 4 pad

__device__ __forceinline__ uint32_t smaddr(const void* p) {
    return (uint32_t)__cvta_generic_to_shared(p);
}
__device__ __forceinline__ void cpa16(uint32_t dst, const void* src) {
    asm volatile("cp.async.cg.shared.global [%0], [%1], 16;" :: "r"(dst), "l"(src));
}
__device__ __forceinline__ void cpa16z(uint32_t dst, const void* src) {
    asm volatile("cp.async.cg.shared.global [%0], [%1], 16, 0;" :: "r"(dst), "l"(src));
}
#define CP_COMMIT() asm volatile("cp.async.commit_group;")
#define CP_WAIT0()  asm volatile("cp.async.wait_group 0;")
#define CP_WAIT1()  asm volatile("cp.async.wait_group 1;")

__device__ __forceinline__ uint32_t f2tf(float x) {
    uint32_t r; asm("cvt.rna.tf32.f32 %0, %1;" : "=r"(r) : "f"(x)); return r;
}
__device__ __forceinline__ uint32_t rna_bits(uint32_t u) {
    return f2tf(__uint_as_float(u));
}
__device__ __forceinline__ void mma8(float* d, const uint32_t* a, uint32_t b0, uint32_t b1) {
    asm("mma.sync.aligned.m16n8k8.row.col.f32.tf32.tf32.f32 "
        "{%0,%1,%2,%3}, {%4,%5,%6,%7}, {%8,%9}, {%0,%1,%2,%3};"
        : "+f"(d[0]), "+f"(d[1]), "+f"(d[2]), "+f"(d[3])
        : "r"(a[0]), "r"(a[1]), "r"(a[2]), "r"(a[3]), "r"(b0), "r"(b1));
}

// ---- static device scratch ----
__device__ float g_Qh[BH*SS*DK];     // tf32-exact values
__device__ float g_Kh[BH*SS*DK];     // tf32-exact values
__device__ float g_WT[2*DD*DD];      // transposed + tf32-rounded Wq, Wk
__device__ float g_lb[BH*SS];
__device__ float g_w [BH*SS];
__device__ float g_ypart[16*BB*HH*DD];
__device__ float g_csp[64*DD];
__device__ float g_outp[64*DD];
__device__ int   g_qidx[BB*SS];
__device__ int   g_cnt [BB];
__device__ float g_cntf[BB];

// ---------------------------------------------------------------------------
// Kernel 0: deterministic mask compaction
// ---------------------------------------------------------------------------
__global__ void k_compact(const int* __restrict__ mask) {
    int b = blockIdx.x;
    int tid = threadIdx.x;
    __shared__ int cnts[256];
    __shared__ int offs[256];
    int base = tid * 8;
    int loc[8];
    int c = 0;
#pragma unroll
    for (int i = 0; i < 8; i++) { loc[i] = mask[b*SS + base + i]; c += (loc[i] != 0); }
    cnts[tid] = c;
    __syncthreads();
    if (tid == 0) {
        int run = 0;
        for (int i = 0; i < 256; i++) { offs[i] = run; run += cnts[i]; }
        g_cnt[b] = run;
        g_cntf[b] = (float)run;
    }
    __syncthreads();
    int o = offs[tid];
#pragma unroll
    for (int i = 0; i < 8; i++) {
        if (loc[i] != 0) { g_qidx[b*SS + o] = base + i; o++; }
    }
}

// ---------------------------------------------------------------------------
// Kernel 0b: transpose + tf32-round W -> g_WT[z]   grid (32,32,2)
// ---------------------------------------------------------------------------
__global__ void k_wtrans(const float* __restrict__ Wq, const float* __restrict__ Wk) {
    __shared__ float t[32][33];
    int sel = blockIdx.z;
    const float* Wsrc = sel ? Wk : Wq;
    float* Wdst = g_WT + (size_t)sel * DD * DD;
    int bx = blockIdx.x * 32, by = blockIdx.y * 32;
    int x = threadIdx.x & 31, y4 = (threadIdx.x >> 5) * 4;
#pragma unroll
    for (int i = 0; i < 4; i++)
        t[y4 + i][x] = Wsrc[(size_t)(by + y4 + i) * DD + bx + x];
    __syncthreads();
#pragma unroll
    for (int i = 0; i < 4; i++)
        Wdst[(size_t)(bx + y4 + i) * DD + by + x] =
            __uint_as_float(f2tf(t[x][y4 + i]));
}

// ---------------------------------------------------------------------------
// Kernel 1: both projection GEMMs in one launch (z = 0:Q, 1:K).   [R12 version]
// ---------------------------------------------------------------------------
__global__ __launch_bounds__(256) void k_proj(
    const float* __restrict__ Xq, const float* __restrict__ Xk,
    const float* __restrict__ bq, const float* __restrict__ bk)
{
    extern __shared__ __align__(16) uint32_t smu[];
    int which = blockIdx.z;
    const float* X    = which ? Xk : Xq;
    const float* Wt   = g_WT + (size_t)which * DD * DD;
    const float* bias = which ? bk : bq;
    float scale = which ? 1.0f : QSCALE;
    float* Out = which ? g_Kh : g_Qh;

    int tid = threadIdx.x;
    int w = tid >> 5, lane = tid & 31;
    int g = lane >> 2, t = lane & 3;
    int m0 = blockIdx.x * 128;
    int n0 = blockIdx.y * 128;

#define STAGE_P(s, k0)                                                           \
    {                                                                            \
        uint32_t* B_ = smu + (s) * 256 * PADP;                                   \
        _Pragma("unroll")                                                        \
        for (int i_ = 0; i_ < 8; i_++) {                                         \
            int idx_ = tid + 256 * i_;                                           \
            int row_ = idx_ >> 3, f4_ = idx_ & 7;                                \
            const float* src_ = (row_ < 128)                                     \
                ? (X  + (size_t)(m0 + row_) * DD + (k0) + f4_*4)                 \
                : (Wt + (size_t)(n0 + row_ - 128) * DD + (k0) + f4_*4);          \
            cpa16(smaddr(B_ + row_*PADP + f4_*4), src_);                         \
        }                                                                        \
    }

    float Dp[16][4];
#pragma unroll
    for (int nc = 0; nc < 16; nc++)
#pragma unroll
        for (int j = 0; j < 4; j++) Dp[nc][j] = 0.f;

    STAGE_P(0, 0); CP_COMMIT();
    for (int kt = 0; kt < 32; kt++) {
        if (kt < 31) { STAGE_P((kt + 1) & 1, (kt + 1) * 32); CP_COMMIT(); }
        if (kt < 31) { CP_WAIT1(); } else { CP_WAIT0(); }
        __syncthreads();
        uint32_t* Xs = smu + (kt & 1) * 256 * PADP;
        uint32_t* Ws = Xs + 128 * PADP;
        uint32_t A[4][4];
#pragma unroll
        for (int kc = 0; kc < 4; kc++) {
            int r0 = (w*16 + g)*PADP + t + 8*kc;
            A[kc][0] = rna_bits(Xs[r0]);
            A[kc][1] = rna_bits(Xs[r0 + 8*PADP]);
            A[kc][2] = rna_bits(Xs[r0 + 4]);
            A[kc][3] = rna_bits(Xs[r0 + 8*PADP + 4]);
        }
#pragma unroll
        for (int nc = 0; nc < 16; nc++) {
            int nb = (nc*8 + g)*PADP + t;
#pragma unroll
            for (int kc = 0; kc < 4; kc++)
                mma8(Dp[nc], A[kc], Ws[nb + 8*kc], Ws[nb + 8*kc + 4]);
        }
        __syncthreads();
    }
    int row0 = m0 + w*16 + g;
#pragma unroll
    for (int nc = 0; nc < 16; nc++) {
        int col = n0 + nc*8 + 2*t;
        float bx = bias[col], by = bias[col+1];
        int h = col >> 6, dd = col & 63;
        {
            int b_ = row0 >> 11, s = row0 & 2047;
            float2 o = make_float2(
                __uint_as_float(f2tf((Dp[nc][0] + bx) * scale)),
                __uint_as_float(f2tf((Dp[nc][1] + by) * scale)));
            *(float2*)(Out + (((size_t)(b_*HH + h) * SS + s) << 6) + dd) = o;
        }
        {
            int row1 = row0 + 8;
            int b_ = row1 >> 11, s = row1 & 2047;
            float2 o = make_float2(
                __uint_as_float(f2tf((Dp[nc][2] + bx) * scale)),
                __uint_as_float(f2tf((Dp[nc][3] + by) * scale)));
            *(float2*)(Out + (((size_t)(b_*HH + h) * SS + s) << 6) + dd) = o;
        }
    }
#undef STAGE_P
}

// ---------------------------------------------------------------------------
// Kernel 2 (pass A): lb[q] via tf32 mma; LDS.64 frags.   [R12 version, proven]
// ---------------------------------------------------------------------------
__global__ __launch_bounds__(256) void k_lsum() {
    extern __shared__ __align__(16) uint32_t smu[];
    uint32_t* Qs = smu;

    int qt = blockIdx.x, bh = blockIdx.y;
    int b = bh >> 4;
    int cnt = g_cnt[b];
    if (qt * 128 >= cnt) return;
    int tid = threadIdx.x;
    int w = tid >> 5, lane = tid & 31;
    int g = lane >> 2, t = lane & 3;
    const float* Qbase = g_Qh + (size_t)bh * SS * 64;
    const float* Kbase = g_Kh + (size_t)bh * SS * 64;

#pragma unroll
    for (int i = 0; i < 8; i++) {
        int idx = tid + 256 * i;
        int row = idx >> 4, d4 = idx & 15;
        int ci = qt*128 + row;
        uint32_t dst = smaddr(Qs + row*PADL + d4*4);
        if (ci < cnt) {
            int s = g_qidx[b*SS + ci];
            cpa16(dst, Qbase + ((size_t)s << 6) + d4*4);
        } else {
            cpa16z(dst, Qbase);
        }
    }
    CP_COMMIT();

#define STAGE_K(kt, s)                                                           \
    {                                                                            \
        uint32_t* Kb_ = smu + 128*PADL + (s) * 128 * PADL;                       \
        _Pragma("unroll")                                                        \
        for (int i_ = 0; i_ < 8; i_++) {                                         \
            int idx_ = tid + 256 * i_;                                           \
            int row_ = idx_ >> 4, d4_ = idx_ & 15;                               \
            cpa16(smaddr(Kb_ + row_*PADL + d4_*4),                               \
                  Kbase + ((size_t)((kt)*128 + row_) << 6) + d4_*4);             \
        }                                                                        \
    }

    STAGE_K(0, 0); CP_COMMIT();
    CP_WAIT1();
    __syncthreads();
    uint32_t A[8][4];
#pragma unroll
    for (int kc = 0; kc < 8; kc++) {
        int r0 = (w*16 + g)*PADL + 8*kc + 2*t;
        uint2 pa0 = *(const uint2*)(Qs + r0);
        uint2 pa1 = *(const uint2*)(Qs + r0 + 8*PADL);
        A[kc][0] = pa0.x; A[kc][2] = pa0.y;
        A[kc][1] = pa1.x; A[kc][3] = pa1.y;
    }
    float rs_lo = 0.f, rs_hi = 0.f;
    for (int kt = 0; kt < 16; kt++) {
        if (kt < 15) { STAGE_K(kt + 1, (kt + 1) & 1); CP_COMMIT(); }
        if (kt < 15) { CP_WAIT1(); } else { CP_WAIT0(); }
        __syncthreads();
        uint32_t* Ks = smu + 128*PADL + (kt & 1) * 128 * PADL;
#pragma unroll 4
        for (int nc = 0; nc < 16; nc++) {
            float c[4] = {0.f, 0.f, 0.f, 0.f};
            int nb = (nc*8 + g)*PADL + 2*t;
#pragma unroll
            for (int kc = 0; kc < 8; kc++) {
                uint2 pb = *(const uint2*)(Ks + nb + 8*kc);
                mma8(c, A[kc], pb.x, pb.y);
            }
            rs_lo += exp2f(c[0]) + exp2f(c[1]);
            rs_hi += exp2f(c[2]) + exp2f(c[3]);
        }
        __syncthreads();
    }
    rs_lo += __shfl_xor_sync(0xffffffffu, rs_lo, 1);
    rs_lo += __shfl_xor_sync(0xffffffffu, rs_lo, 2);
    rs_hi += __shfl_xor_sync(0xffffffffu, rs_hi, 1);
    rs_hi += __shfl_xor_sync(0xffffffffu, rs_hi, 2);
    if (t == 0) {
        int ci = qt*128 + w*16 + g;
        if (ci < cnt)     g_lb[bh*SS + ci]     = log2f(rs_lo);
        if (ci + 8 < cnt) g_lb[bh*SS + ci + 8] = log2f(rs_hi);
    }
#undef STAGE_K
}

// ---------------------------------------------------------------------------
// Kernel 3 (pass B): w[k] via tf32 mma.   [R12 version: scalar frags, shared wp]
// dyn smem 108544 B (2 CTA/SM). grid (16, 32).
// ---------------------------------------------------------------------------
__global__ __launch_bounds__(256) void k_wsum() {
    extern __shared__ __align__(16) uint32_t smu[];
    uint32_t* Ks = smu;                         // [128][PADW]
    float* wp = (float*)(smu + 3*128*PADW);     // [8][128]

    int kt = blockIdx.x, bh = blockIdx.y;
    int b = bh >> 4;
    int cnt = g_cnt[b];
    int tid = threadIdx.x;
    int w = tid >> 5, lane = tid & 31;
    int g = lane >> 2, t = lane & 3;
    const float* Qbase = g_Qh + (size_t)bh * SS * 64;
    const float* Kbase = g_Kh + (size_t)bh * SS * 64;
    const float* lbp = g_lb + (size_t)bh * SS;

#pragma unroll
    for (int i = 0; i < 4; i++) wp[tid + 256*i] = 0.f;

#pragma unroll
    for (int i = 0; i < 8; i++) {
        int idx = tid + 256 * i;
        int row = idx >> 4, d4 = idx & 15;
        cpa16(smaddr(Ks + row*PADW + d4*4),
              Kbase + ((size_t)(kt*128 + row) << 6) + d4*4);
    }
    CP_COMMIT();

#define STAGE_QT(qt, s)                                                          \
    {                                                                            \
        uint32_t* Qb_ = smu + 128*PADW + (s) * 128 * PADW;                       \
        _Pragma("unroll")                                                        \
        for (int i_ = 0; i_ < 8; i_++) {                                         \
            int idx_ = tid + 256 * i_;                                           \
            int row_ = idx_ >> 4, d4_ = idx_ & 15;                               \
            int ci_ = (qt)*128 + row_;                                           \
            uint32_t dst_ = smaddr(Qb_ + row_*PADW + d4_*4);                     \
            if (ci_ < cnt) {                                                     \
                int s_ = g_qidx[b*SS + ci_];                                     \
                cpa16(dst_, Qbase + ((size_t)s_ << 6) + d4_*4);                  \
            } else {                                                             \
                cpa16z(dst_, Qbase);                                             \
            }                                                                    \
        }                                                                        \
    }

    int nqt = (cnt + 127) >> 7;
    if (nqt > 0) { STAGE_QT(0, 0); CP_COMMIT(); }

    for (int qt = 0; qt < nqt; qt++) {
        if (qt + 1 < nqt) { STAGE_QT(qt + 1, (qt + 1) & 1); CP_COMMIT(); }
        if (qt + 1 < nqt) { CP_WAIT1(); } else { CP_WAIT0(); }
        __syncthreads();
        uint32_t* Qs = smu + 128*PADW + (qt & 1) * 128 * PADW;
        int ci0 = qt*128 + w*16 + g;
        float lb_lo = (ci0     < cnt) ? lbp[ci0]     : 1e9f;
        float lb_hi = (ci0 + 8 < cnt) ? lbp[ci0 + 8] : 1e9f;
        uint32_t A[8][4];
#pragma unroll
        for (int kc = 0; kc < 8; kc++) {
            int r0 = (w*16 + g)*PADW + t + 8*kc;
            A[kc][0] = Qs[r0];
            A[kc][1] = Qs[r0 + 8*PADW];
            A[kc][2] = Qs[r0 + 4];
            A[kc][3] = Qs[r0 + 8*PADW + 4];
        }
#pragma unroll 4
        for (int nc = 0; nc < 16; nc++) {
            float c[4] = {0.f, 0.f, 0.f, 0.f};
            int nb = (nc*8 + g)*PADW + t;
#pragma unroll
            for (int kc = 0; kc < 8; kc++)
                mma8(c, A[kc], Ks[nb + 8*kc], Ks[nb + 8*kc + 4]);
            float p0 = exp2f(c[0] - lb_lo) + exp2f(c[2] - lb_hi);
            float p1 = exp2f(c[1] - lb_lo) + exp2f(c[3] - lb_hi);
            p0 += __shfl_xor_sync(0xffffffffu, p0, 4);
            p0 += __shfl_xor_sync(0xffffffffu, p0, 8);
            p0 += __shfl_xor_sync(0xffffffffu, p0, 16);
            p1 += __shfl_xor_sync(0xffffffffu, p1, 4);
            p1 += __shfl_xor_sync(0xffffffffu, p1, 8);
            p1 += __shfl_xor_sync(0xffffffffu, p1, 16);
            if (g == 0) {
                wp[w*128 + nc*8 + 2*t]     += p0;
                wp[w*128 + nc*8 + 2*t + 1] += p1;
            }
        }
        __syncthreads();
    }
    CP_WAIT0();
    __syncthreads();
    if (tid < 128) {
        float wv = 0.f;
#pragma unroll
        for (int i = 0; i < 8; i++) wv += wp[i*128 + tid];
        g_w[bh*SS + kt*128 + tid] = wv;
    }
#undef STAGE_QT
}

// ---------------------------------------------------------------------------
// Kernel 4: y-partials (unchanged R10 version)
// ---------------------------------------------------------------------------
__global__ __launch_bounds__(256) void k_ypart(const float* __restrict__ v) {
    int id = blockIdx.x;
    int kt = id & 15;
    int jt = (id >> 4) & 3;
    int b  = id >> 6;
    __shared__ float wsh[16][128];
    int tid = threadIdx.x;
#pragma unroll
    for (int i = 0; i < 8; i++) {
        int idx = tid + 256 * i;
        int h = idx >> 7, kk = idx & 127;
        wsh[h][kk] = g_w[(b*HH + h) * SS + kt*128 + kk];
    }
    __syncthreads();
    int j = jt * 256 + tid;
    float acc[16];
#pragma unroll
    for (int h = 0; h < 16; h++) acc[h] = 0.f;
    const float* vb = v + ((size_t)b * SS + kt*128) * 1024 + j;
    for (int kk = 0; kk < 128; kk++) {
        float vv = vb[(size_t)kk * 1024];
#pragma unroll
        for (int h = 0; h < 16; h++) acc[h] += wsh[h][kk] * vv;
    }
#pragma unroll
    for (int h = 0; h < 16; h++)
        g_ypart[((size_t)(kt*BB + b) * HH + h) * DD + j] = acc[h];
}

// ---------------------------------------------------------------------------
// Kernel 5 (FUSED yred + cs_part): block (b, jc) reduces its own y slice
// from the 16 split-k partials, then computes csp partials.
// ---------------------------------------------------------------------------
__global__ __launch_bounds__(256) void k_cs_part(const float* __restrict__ Wv) {
    __shared__ float ys[16][32];    // y[b][h][j_local]
    int bid = blockIdx.x;
    int b = bid >> 5, jc = bid & 31;
    int tid = threadIdx.x;

    // reduce y slice: 512 values, 2 per thread
#pragma unroll
    for (int r = 0; r < 2; r++) {
        int idx = tid + 256 * r;      // 0..511
        int h = idx >> 5, jl = idx & 31;
        int j = jc*32 + jl;
        float s = 0.f;
#pragma unroll
        for (int kt = 0; kt < 16; kt++)
            s += g_ypart[((size_t)(kt*BB + b) * HH + h) * DD + j];
        ys[h][jl] = s;
    }
    __syncthreads();

    int c0 = tid * 4;
    int h = tid >> 4;                 // c0 >> 6
    float4 s = make_float4(0.f, 0.f, 0.f, 0.f);
#pragma unroll 8
    for (int jl = 0; jl < 32; jl++) {
        float yv = ys[h][jl];
        float4 w4 = *(const float4*)(Wv + (size_t)(jc*32 + jl) * 1024 + c0);
        s.x += yv * w4.x; s.y += yv * w4.y; s.z += yv * w4.z; s.w += yv * w4.w;
    }
    *(float4*)(g_csp + (size_t)bid * DD + c0) = s;
}

// ---------------------------------------------------------------------------
// Kernel 6 (FUSED cs_red + out_part): block (b, jc) reduces its own 32 cs
// values (+ cnt*bv), then computes outp partials.
// ---------------------------------------------------------------------------
__global__ __launch_bounds__(256) void k_out_part(
    const float* __restrict__ Wo, const float* __restrict__ bv)
{
    __shared__ float css[32];
    int bid = blockIdx.x;
    int b = bid >> 5, jc = bid & 31;
    int tid = threadIdx.x;

    if (tid < 32) {
        int c = jc*32 + tid;
        float s = 0.f;
#pragma unroll
        for (int p = 0; p < 32; p++) s += g_csp[(size_t)(b*32 + p) * DD + c];
        css[tid] = s + g_cntf[b] * bv[c];
    }
    __syncthreads();

    int d0 = tid * 4;
    float4 s = make_float4(0.f, 0.f, 0.f, 0.f);
#pragma unroll 8
    for (int cl = 0; cl < 32; cl++) {
        float cv = css[cl];
        float4 w4 = *(const float4*)(Wo + (size_t)(jc*32 + cl) * 1024 + d0);
        s.x += cv * w4.x; s.y += cv * w4.y; s.z += cv * w4.z; s.w += cv * w4.w;
    }
    *(float4*)(g_outp + (size_t)bid * DD + d0) = s;
}

// ---------------------------------------------------------------------------
// Kernel 7: final reduce
// ---------------------------------------------------------------------------
__global__ void k_out_red(const float* __restrict__ bo, float* __restrict__ out) {
    int idx = blockIdx.x * 256 + threadIdx.x;   // 0..2047
    int b = idx >> 10, d = idx & 1023;
    float s = 0.f;
#pragma unroll
    for (int jc = 0; jc < 32; jc++) s += g_outp[(size_t)(b*32 + jc) * DD + d];
    out[idx] = s + g_cntf[b] * bo[d];
}

// ---------------------------------------------------------------------------
extern "C" void kernel_launch(void* const* d_in, const int* in_sizes, int n_in,
                              void* d_out, int out_size) {
    const float* q    = (const float*)d_in[0];
    const float* k    = (const float*)d_in[1];
    const float* v    = (const float*)d_in[2];
    const int*   mask = (const int*)  d_in[3];
    const float* Wq   = (const float*)d_in[4];
    const float* bq   = (const float*)d_in[5];
    const float* Wk   = (const float*)d_in[6];
    const float* bk   = (const float*)d_in[7];
    const float* Wv   = (const float*)d_in[8];
    const float* bv   = (const float*)d_in[9];
    const float* Wo   = (const float*)d_in[10];
    const float* bo   = (const float*)d_in[11];
    float* out = (float*)d_out;

    const int SM_PROJ = 2 * 256 * PADP * 4;             // 73728  (3 CTA/SM)
    const int SM_LSUM = 3 * 128 * PADL * 4;             // 110592 (2 CTA/SM)
    const int SM_WSUM = 3 * 128 * PADW * 4 + 4096;      // 108544 (2 CTA/SM)

    cudaFuncSetAttribute(k_proj, cudaFuncAttributeMaxDynamicSharedMemorySize, SM_PROJ);
    cudaFuncSetAttribute(k_lsum, cudaFuncAttributeMaxDynamicSharedMemorySize, SM_LSUM);
    cudaFuncSetAttribute(k_wsum, cudaFuncAttributeMaxDynamicSharedMemorySize, SM_WSUM);

    k_compact<<<BB, 256>>>(mask);
    k_wtrans<<<dim3(32, 32, 2), 256>>>(Wq, Wk);
    k_proj<<<dim3(32, 8, 2), 256, SM_PROJ>>>(q, k, bq, bk);
    k_lsum<<<dim3(16, 32), 256, SM_LSUM>>>();
    k_wsum<<<dim3(16, 32), 256, SM_WSUM>>>();
    k_ypart<<<128, 256>>>(v);
    k_cs_part<<<64, 256>>>(Wv);
    k_out_part<<<64, 256>>>(Wo, bv);
    k_out_red<<<8, 256>>>(bo, out);
}

// round 15
// speedup vs baseline: 1.0956x; 1.0648x over previous
#include <cuda_runtime.h>
#include <math.h>
#include <stdint.h>

// Problem constants (B=2, S=2048, D=1024, H=16, Dk=64)
#define BB 2
#define SS 2048
#define DD 1024
#define HH 16
#define DK 64
#define BH (BB*HH)

#define QSCALE (0.125f * 1.44269504088896340736f)
#define PADL 72   // k_lsum/k_wsum: 64-float rows + 8 pad (LDS.64 conflict-free)
#define PADP 36   // k_proj: 32-float rows + 4 pad

__device__ __forceinline__ uint32_t smaddr(const void* p) {
    return (uint32_t)__cvta_generic_to_shared(p);
}
__device__ __forceinline__ void cpa16(uint32_t dst, const void* src) {
    asm volatile("cp.async.cg.shared.global [%0], [%1], 16;" :: "r"(dst), "l"(src));
}
__device__ __forceinline__ void cpa16z(uint32_t dst, const void* src) {
    asm volatile("cp.async.cg.shared.global [%0], [%1], 16, 0;" :: "r"(dst), "l"(src));
}
#define CP_COMMIT() asm volatile("cp.async.commit_group;")
#define CP_WAIT0()  asm volatile("cp.async.wait_group 0;")
#define CP_WAIT1()  asm volatile("cp.async.wait_group 1;")

__device__ __forceinline__ uint32_t f2tf(float x) {
    uint32_t r; asm("cvt.rna.tf32.f32 %0, %1;" : "=r"(r) : "f"(x)); return r;
}
__device__ __forceinline__ uint32_t rna_bits(uint32_t u) {
    return f2tf(__uint_as_float(u));
}
__device__ __forceinline__ void mma8(float* d, const uint32_t* a, uint32_t b0, uint32_t b1) {
    asm("mma.sync.aligned.m16n8k8.row.col.f32.tf32.tf32.f32 "
        "{%0,%1,%2,%3}, {%4,%5,%6,%7}, {%8,%9}, {%0,%1,%2,%3};"
        : "+f"(d[0]), "+f"(d[1]), "+f"(d[2]), "+f"(d[3])
        : "r"(a[0]), "r"(a[1]), "r"(a[2]), "r"(a[3]), "r"(b0), "r"(b1));
}

// ---- static device scratch ----
__device__ float g_Qh[BH*SS*DK];     // tf32-exact values
__device__ float g_Kh[BH*SS*DK];     // tf32-exact values
__device__ float g_WT[2*DD*DD];      // transposed + tf32-rounded Wq, Wk
__device__ float g_lb[BH*SS];
__device__ float g_w [BH*SS];
__device__ float g_ypart[16*BB*HH*DD];
__device__ float g_csp[64*DD];
__device__ float g_outp[64*DD];
__device__ int   g_qidx[BB*SS];
__device__ int   g_cnt [BB];
__device__ float g_cntf[BB];

// ---------------------------------------------------------------------------
// Kernel 0: deterministic mask compaction
// ---------------------------------------------------------------------------
__global__ void k_compact(const int* __restrict__ mask) {
    int b = blockIdx.x;
    int tid = threadIdx.x;
    __shared__ int cnts[256];
    __shared__ int offs[256];
    int base = tid * 8;
    int loc[8];
    int c = 0;
#pragma unroll
    for (int i = 0; i < 8; i++) { loc[i] = mask[b*SS + base + i]; c += (loc[i] != 0); }
    cnts[tid] = c;
    __syncthreads();
    if (tid == 0) {
        int run = 0;
        for (int i = 0; i < 256; i++) { offs[i] = run; run += cnts[i]; }
        g_cnt[b] = run;
        g_cntf[b] = (float)run;
    }
    __syncthreads();
    int o = offs[tid];
#pragma unroll
    for (int i = 0; i < 8; i++) {
        if (loc[i] != 0) { g_qidx[b*SS + o] = base + i; o++; }
    }
}

// ---------------------------------------------------------------------------
// Kernel 0b: transpose + tf32-round W -> g_WT[z]   grid (32,32,2)
// ---------------------------------------------------------------------------
__global__ void k_wtrans(const float* __restrict__ Wq, const float* __restrict__ Wk) {
    __shared__ float t[32][33];
    int sel = blockIdx.z;
    const float* Wsrc = sel ? Wk : Wq;
    float* Wdst = g_WT + (size_t)sel * DD * DD;
    int bx = blockIdx.x * 32, by = blockIdx.y * 32;
    int x = threadIdx.x & 31, y4 = (threadIdx.x >> 5) * 4;
#pragma unroll
    for (int i = 0; i < 4; i++)
        t[y4 + i][x] = Wsrc[(size_t)(by + y4 + i) * DD + bx + x];
    __syncthreads();
#pragma unroll
    for (int i = 0; i < 4; i++)
        Wdst[(size_t)(bx + y4 + i) * DD + by + x] =
            __uint_as_float(f2tf(t[x][y4 + i]));
}

// ---------------------------------------------------------------------------
// Kernel 1: both projection GEMMs in one launch (z = 0:Q, 1:K).   [R12 version]
// ---------------------------------------------------------------------------
__global__ __launch_bounds__(256) void k_proj(
    const float* __restrict__ Xq, const float* __restrict__ Xk,
    const float* __restrict__ bq, const float* __restrict__ bk)
{
    extern __shared__ __align__(16) uint32_t smu[];
    int which = blockIdx.z;
    const float* X    = which ? Xk : Xq;
    const float* Wt   = g_WT + (size_t)which * DD * DD;
    const float* bias = which ? bk : bq;
    float scale = which ? 1.0f : QSCALE;
    float* Out = which ? g_Kh : g_Qh;

    int tid = threadIdx.x;
    int w = tid >> 5, lane = tid & 31;
    int g = lane >> 2, t = lane & 3;
    int m0 = blockIdx.x * 128;
    int n0 = blockIdx.y * 128;

#define STAGE_P(s, k0)                                                           \
    {                                                                            \
        uint32_t* B_ = smu + (s) * 256 * PADP;                                   \
        _Pragma("unroll")                                                        \
        for (int i_ = 0; i_ < 8; i_++) {                                         \
            int idx_ = tid + 256 * i_;                                           \
            int row_ = idx_ >> 3, f4_ = idx_ & 7;                                \
            const float* src_ = (row_ < 128)                                     \
                ? (X  + (size_t)(m0 + row_) * DD + (k0) + f4_*4)                 \
                : (Wt + (size_t)(n0 + row_ - 128) * DD + (k0) + f4_*4);          \
            cpa16(smaddr(B_ + row_*PADP + f4_*4), src_);                         \
        }                                                                        \
    }

    float Dp[16][4];
#pragma unroll
    for (int nc = 0; nc < 16; nc++)
#pragma unroll
        for (int j = 0; j < 4; j++) Dp[nc][j] = 0.f;

    STAGE_P(0, 0); CP_COMMIT();
    for (int kt = 0; kt < 32; kt++) {
        if (kt < 31) { STAGE_P((kt + 1) & 1, (kt + 1) * 32); CP_COMMIT(); }
        if (kt < 31) { CP_WAIT1(); } else { CP_WAIT0(); }
        __syncthreads();
        uint32_t* Xs = smu + (kt & 1) * 256 * PADP;
        uint32_t* Ws = Xs + 128 * PADP;
        uint32_t A[4][4];
#pragma unroll
        for (int kc = 0; kc < 4; kc++) {
            int r0 = (w*16 + g)*PADP + t + 8*kc;
            A[kc][0] = rna_bits(Xs[r0]);
            A[kc][1] = rna_bits(Xs[r0 + 8*PADP]);
            A[kc][2] = rna_bits(Xs[r0 + 4]);
            A[kc][3] = rna_bits(Xs[r0 + 8*PADP + 4]);
        }
#pragma unroll
        for (int nc = 0; nc < 16; nc++) {
            int nb = (nc*8 + g)*PADP + t;
#pragma unroll
            for (int kc = 0; kc < 4; kc++)
                mma8(Dp[nc], A[kc], Ws[nb + 8*kc], Ws[nb + 8*kc + 4]);
        }
        __syncthreads();
    }
    int row0 = m0 + w*16 + g;
#pragma unroll
    for (int nc = 0; nc < 16; nc++) {
        int col = n0 + nc*8 + 2*t;
        float bx = bias[col], by = bias[col+1];
        int h = col >> 6, dd = col & 63;
        {
            int b_ = row0 >> 11, s = row0 & 2047;
            float2 o = make_float2(
                __uint_as_float(f2tf((Dp[nc][0] + bx) * scale)),
                __uint_as_float(f2tf((Dp[nc][1] + by) * scale)));
            *(float2*)(Out + (((size_t)(b_*HH + h) * SS + s) << 6) + dd) = o;
        }
        {
            int row1 = row0 + 8;
            int b_ = row1 >> 11, s = row1 & 2047;
            float2 o = make_float2(
                __uint_as_float(f2tf((Dp[nc][2] + bx) * scale)),
                __uint_as_float(f2tf((Dp[nc][3] + by) * scale)));
            *(float2*)(Out + (((size_t)(b_*HH + h) * SS + s) << 6) + dd) = o;
        }
    }
#undef STAGE_P
}

// ---------------------------------------------------------------------------
// Kernel 2 (pass A): lb[q] via tf32 mma; LDS.64 frags.   [R12 version, proven]
// ---------------------------------------------------------------------------
__global__ __launch_bounds__(256) void k_lsum() {
    extern __shared__ __align__(16) uint32_t smu[];
    uint32_t* Qs = smu;

    int qt = blockIdx.x, bh = blockIdx.y;
    int b = bh >> 4;
    int cnt = g_cnt[b];
    if (qt * 128 >= cnt) return;
    int tid = threadIdx.x;
    int w = tid >> 5, lane = tid & 31;
    int g = lane >> 2, t = lane & 3;
    const float* Qbase = g_Qh + (size_t)bh * SS * 64;
    const float* Kbase = g_Kh + (size_t)bh * SS * 64;

#pragma unroll
    for (int i = 0; i < 8; i++) {
        int idx = tid + 256 * i;
        int row = idx >> 4, d4 = idx & 15;
        int ci = qt*128 + row;
        uint32_t dst = smaddr(Qs + row*PADL + d4*4);
        if (ci < cnt) {
            int s = g_qidx[b*SS + ci];
            cpa16(dst, Qbase + ((size_t)s << 6) + d4*4);
        } else {
            cpa16z(dst, Qbase);
        }
    }
    CP_COMMIT();

#define STAGE_K(kt, s)                                                           \
    {                                                                            \
        uint32_t* Kb_ = smu + 128*PADL + (s) * 128 * PADL;                       \
        _Pragma("unroll")                                                        \
        for (int i_ = 0; i_ < 8; i_++) {                                         \
            int idx_ = tid + 256 * i_;                                           \
            int row_ = idx_ >> 4, d4_ = idx_ & 15;                               \
            cpa16(smaddr(Kb_ + row_*PADL + d4_*4),                               \
                  Kbase + ((size_t)((kt)*128 + row_) << 6) + d4_*4);             \
        }                                                                        \
    }

    STAGE_K(0, 0); CP_COMMIT();
    CP_WAIT1();
    __syncthreads();
    uint32_t A[8][4];
#pragma unroll
    for (int kc = 0; kc < 8; kc++) {
        int r0 = (w*16 + g)*PADL + 8*kc + 2*t;
        uint2 pa0 = *(const uint2*)(Qs + r0);
        uint2 pa1 = *(const uint2*)(Qs + r0 + 8*PADL);
        A[kc][0] = pa0.x; A[kc][2] = pa0.y;
        A[kc][1] = pa1.x; A[kc][3] = pa1.y;
    }
    float rs_lo = 0.f, rs_hi = 0.f;
    for (int kt = 0; kt < 16; kt++) {
        if (kt < 15) { STAGE_K(kt + 1, (kt + 1) & 1); CP_COMMIT(); }
        if (kt < 15) { CP_WAIT1(); } else { CP_WAIT0(); }
        __syncthreads();
        uint32_t* Ks = smu + 128*PADL + (kt & 1) * 128 * PADL;
#pragma unroll 4
        for (int nc = 0; nc < 16; nc++) {
            float c[4] = {0.f, 0.f, 0.f, 0.f};
            int nb = (nc*8 + g)*PADL + 2*t;
#pragma unroll
            for (int kc = 0; kc < 8; kc++) {
                uint2 pb = *(const uint2*)(Ks + nb + 8*kc);
                mma8(c, A[kc], pb.x, pb.y);
            }
            rs_lo += exp2f(c[0]) + exp2f(c[1]);
            rs_hi += exp2f(c[2]) + exp2f(c[3]);
        }
        __syncthreads();
    }
    rs_lo += __shfl_xor_sync(0xffffffffu, rs_lo, 1);
    rs_lo += __shfl_xor_sync(0xffffffffu, rs_lo, 2);
    rs_hi += __shfl_xor_sync(0xffffffffu, rs_hi, 1);
    rs_hi += __shfl_xor_sync(0xffffffffu, rs_hi, 2);
    if (t == 0) {
        int ci = qt*128 + w*16 + g;
        if (ci < cnt)     g_lb[bh*SS + ci]     = log2f(rs_lo);
        if (ci + 8 < cnt) g_lb[bh*SS + ci + 8] = log2f(rs_hi);
    }
#undef STAGE_K
}

// ---------------------------------------------------------------------------
// Kernel 3 (pass B): w[k] via tf32 mma, TRANSPOSED orientation:
// A = persistent K tile (M=keys, frags loaded ONCE), B = Q (N=q columns).
// Column sums accumulate in registers; single shfl tree at end; no wp buffer.
// dyn smem 3*128*PADL*4 + 512 = 111104 B (2 CTA/SM). grid (16, 32).
// ---------------------------------------------------------------------------
__global__ __launch_bounds__(256) void k_wsum() {
    extern __shared__ __align__(16) uint32_t smu[];
    uint32_t* Ks = smu;                         // [128][PADL] keys (persistent)
    float* lbs = (float*)(smu + 3*128*PADL);    // [128]

    int kt = blockIdx.x, bh = blockIdx.y;
    int b = bh >> 4;
    int cnt = g_cnt[b];
    int tid = threadIdx.x;
    int w = tid >> 5, lane = tid & 31;
    int g = lane >> 2, t = lane & 3;
    const float* Qbase = g_Qh + (size_t)bh * SS * 64;
    const float* Kbase = g_Kh + (size_t)bh * SS * 64;
    const float* lbp = g_lb + (size_t)bh * SS;

    // stage persistent 128-key K tile (group 0)
#pragma unroll
    for (int i = 0; i < 8; i++) {
        int idx = tid + 256 * i;
        int row = idx >> 4, d4 = idx & 15;
        cpa16(smaddr(Ks + row*PADL + d4*4),
              Kbase + ((size_t)(kt*128 + row) << 6) + d4*4);
    }
    CP_COMMIT();

    // Layout: Ks [0,128*PADL) ; Qb0 [128*PADL,256*PADL) ; Qb1 [256*PADL,384*PADL) ; lbs after.
#define STAGE_QT(qt, s)                                                          \
    {                                                                            \
        uint32_t* Qb_ = smu + 128*PADL + (s) * 128 * PADL;                       \
        _Pragma("unroll")                                                        \
        for (int i_ = 0; i_ < 8; i_++) {                                         \
            int idx_ = tid + 256 * i_;                                           \
            int row_ = idx_ >> 4, d4_ = idx_ & 15;                               \
            int ci_ = (qt)*128 + row_;                                           \
            uint32_t dst_ = smaddr(Qb_ + row_*PADL + d4_*4);                     \
            if (ci_ < cnt) {                                                     \
                int s_ = g_qidx[b*SS + ci_];                                     \
                cpa16(dst_, Qbase + ((size_t)s_ << 6) + d4_*4);                  \
            } else {                                                             \
                cpa16z(dst_, Qbase);                                             \
            }                                                                    \
        }                                                                        \
    }

    int nqt = (cnt + 127) >> 7;
    if (nqt > 0) { STAGE_QT(0, 0); CP_COMMIT(); }

    // wait for K tile (<=1 group pending leaves group 0 complete), load A frags once
    if (nqt > 0) { CP_WAIT1(); } else { CP_WAIT0(); }
    __syncthreads();
    uint32_t A[8][4];
#pragma unroll
    for (int kc = 0; kc < 8; kc++) {
        int r0 = (w*16 + g)*PADL + 8*kc + 2*t;
        uint2 pa0 = *(const uint2*)(Ks + r0);
        uint2 pa1 = *(const uint2*)(Ks + r0 + 8*PADL);
        A[kc][0] = pa0.x; A[kc][2] = pa0.y;
        A[kc][1] = pa1.x; A[kc][3] = pa1.y;
    }

    float wlo = 0.f, whi = 0.f;
    for (int qt = 0; qt < nqt; qt++) {
        if (qt + 1 < nqt) { STAGE_QT(qt + 1, (qt + 1) & 1); CP_COMMIT(); }
        if (tid < 128) {
            int ci = qt*128 + tid;
            lbs[tid] = (ci < cnt) ? lbp[ci] : 1e9f;
        }
        if (qt + 1 < nqt) { CP_WAIT1(); } else { CP_WAIT0(); }
        __syncthreads();
        uint32_t* Qs = smu + 128*PADL + (qt & 1) * 128 * PADL;
#pragma unroll 4
        for (int nc = 0; nc < 16; nc++) {
            float c[4] = {0.f, 0.f, 0.f, 0.f};
            int nb = (nc*8 + g)*PADL + 2*t;
#pragma unroll
            for (int kc = 0; kc < 8; kc++) {
                uint2 pb = *(const uint2*)(Qs + nb + 8*kc);
                mma8(c, A[kc], pb.x, pb.y);
            }
            float lb0 = lbs[nc*8 + 2*t];
            float lb1 = lbs[nc*8 + 2*t + 1];
            wlo += exp2f(c[0] - lb0) + exp2f(c[1] - lb1);
            whi += exp2f(c[2] - lb0) + exp2f(c[3] - lb1);
        }
        __syncthreads();
    }
    // reduce over the 4 t-lanes (lane = g*4 + t; xor 1,2 mix t bits only)
    wlo += __shfl_xor_sync(0xffffffffu, wlo, 1);
    wlo += __shfl_xor_sync(0xffffffffu, wlo, 2);
    whi += __shfl_xor_sync(0xffffffffu, whi, 1);
    whi += __shfl_xor_sync(0xffffffffu, whi, 2);
    if (t == 0) {
        int key = kt*128 + w*16 + g;
        g_w[bh*SS + key]     = wlo;
        g_w[bh*SS + key + 8] = whi;
    }
#undef STAGE_QT
}

// ---------------------------------------------------------------------------
// Kernel 4: y-partials (unchanged R10 version)
// ---------------------------------------------------------------------------
__global__ __launch_bounds__(256) void k_ypart(const float* __restrict__ v) {
    int id = blockIdx.x;
    int kt = id & 15;
    int jt = (id >> 4) & 3;
    int b  = id >> 6;
    __shared__ float wsh[16][128];
    int tid = threadIdx.x;
#pragma unroll
    for (int i = 0; i < 8; i++) {
        int idx = tid + 256 * i;
        int h = idx >> 7, kk = idx & 127;
        wsh[h][kk] = g_w[(b*HH + h) * SS + kt*128 + kk];
    }
    __syncthreads();
    int j = jt * 256 + tid;
    float acc[16];
#pragma unroll
    for (int h = 0; h < 16; h++) acc[h] = 0.f;
    const float* vb = v + ((size_t)b * SS + kt*128) * 1024 + j;
    for (int kk = 0; kk < 128; kk++) {
        float vv = vb[(size_t)kk * 1024];
#pragma unroll
        for (int h = 0; h < 16; h++) acc[h] += wsh[h][kk] * vv;
    }
#pragma unroll
    for (int h = 0; h < 16; h++)
        g_ypart[((size_t)(kt*BB + b) * HH + h) * DD + j] = acc[h];
}

// ---------------------------------------------------------------------------
// Kernel 5 (FUSED yred + cs_part)
// ---------------------------------------------------------------------------
__global__ __launch_bounds__(256) void k_cs_part(const float* __restrict__ Wv) {
    __shared__ float ys[16][32];
    int bid = blockIdx.x;
    int b = bid >> 5, jc = bid & 31;
    int tid = threadIdx.x;

#pragma unroll
    for (int r = 0; r < 2; r++) {
        int idx = tid + 256 * r;
        int h = idx >> 5, jl = idx & 31;
        int j = jc*32 + jl;
        float s = 0.f;
#pragma unroll
        for (int kt = 0; kt < 16; kt++)
            s += g_ypart[((size_t)(kt*BB + b) * HH + h) * DD + j];
        ys[h][jl] = s;
    }
    __syncthreads();

    int c0 = tid * 4;
    int h = tid >> 4;
    float4 s = make_float4(0.f, 0.f, 0.f, 0.f);
#pragma unroll 8
    for (int jl = 0; jl < 32; jl++) {
        float yv = ys[h][jl];
        float4 w4 = *(const float4*)(Wv + (size_t)(jc*32 + jl) * 1024 + c0);
        s.x += yv * w4.x; s.y += yv * w4.y; s.z += yv * w4.z; s.w += yv * w4.w;
    }
    *(float4*)(g_csp + (size_t)bid * DD + c0) = s;
}

// ---------------------------------------------------------------------------
// Kernel 6 (FUSED cs_red + out_part)
// ---------------------------------------------------------------------------
__global__ __launch_bounds__(256) void k_out_part(
    const float* __restrict__ Wo, const float* __restrict__ bv)
{
    __shared__ float css[32];
    int bid = blockIdx.x;
    int b = bid >> 5, jc = bid & 31;
    int tid = threadIdx.x;

    if (tid < 32) {
        int c = jc*32 + tid;
        float s = 0.f;
#pragma unroll
        for (int p = 0; p < 32; p++) s += g_csp[(size_t)(b*32 + p) * DD + c];
        css[tid] = s + g_cntf[b] * bv[c];
    }
    __syncthreads();

    int d0 = tid * 4;
    float4 s = make_float4(0.f, 0.f, 0.f, 0.f);
#pragma unroll 8
    for (int cl = 0; cl < 32; cl++) {
        float cv = css[cl];
        float4 w4 = *(const float4*)(Wo + (size_t)(jc*32 + cl) * 1024 + d0);
        s.x += cv * w4.x; s.y += cv * w4.y; s.z += cv * w4.z; s.w += cv * w4.w;
    }
    *(float4*)(g_outp + (size_t)bid * DD + d0) = s;
}

// ---------------------------------------------------------------------------
// Kernel 7: final reduce
// ---------------------------------------------------------------------------
__global__ void k_out_red(const float* __restrict__ bo, float* __restrict__ out) {
    int idx = blockIdx.x * 256 + threadIdx.x;
    int b = idx >> 10, d = idx & 1023;
    float s = 0.f;
#pragma unroll
    for (int jc = 0; jc < 32; jc++) s += g_outp[(size_t)(b*32 + jc) * DD + d];
    out[idx] = s + g_cntf[b] * bo[d];
}

// ---------------------------------------------------------------------------
extern "C" void kernel_launch(void* const* d_in, const int* in_sizes, int n_in,
                              void* d_out, int out_size) {
    const float* q    = (const float*)d_in[0];
    const float* k    = (const float*)d_in[1];
    const float* v    = (const float*)d_in[2];
    const int*   mask = (const int*)  d_in[3];
    const float* Wq   = (const float*)d_in[4];
    const float* bq   = (const float*)d_in[5];
    const float* Wk   = (const float*)d_in[6];
    const float* bk   = (const float*)d_in[7];
    const float* Wv   = (const float*)d_in[8];
    const float* bv   = (const float*)d_in[9];
    const float* Wo   = (const float*)d_in[10];
    const float* bo   = (const float*)d_in[11];
    float* out = (float*)d_out;

    const int SM_PROJ = 2 * 256 * PADP * 4;             // 73728  (3 CTA/SM)
    const int SM_LSUM = 3 * 128 * PADL * 4;             // 110592 (2 CTA/SM)
    const int SM_WSUM = 3 * 128 * PADL * 4 + 512;       // 111104 (2 CTA/SM)

    cudaFuncSetAttribute(k_proj, cudaFuncAttributeMaxDynamicSharedMemorySize, SM_PROJ);
    cudaFuncSetAttribute(k_lsum, cudaFuncAttributeMaxDynamicSharedMemorySize, SM_LSUM);
    cudaFuncSetAttribute(k_wsum, cudaFuncAttributeMaxDynamicSharedMemorySize, SM_WSUM);

    k_compact<<<BB, 256>>>(mask);
    k_wtrans<<<dim3(32, 32, 2), 256>>>(Wq, Wk);
    k_proj<<<dim3(32, 8, 2), 256, SM_PROJ>>>(q, k, bq, bk);
    k_lsum<<<dim3(16, 32), 256, SM_LSUM>>>();
    k_wsum<<<dim3(16, 32), 256, SM_WSUM>>>();
    k_ypart<<<128, 256>>>(v);
    k_cs_part<<<64, 256>>>(Wv);
    k_out_part<<<64, 256>>>(Wo, bv);
    k_out_red<<<8, 256>>>(bo, out);
}

// round 16
// speedup vs baseline: 1.0981x; 1.0022x over previous
#include <cuda_runtime.h>
#include <math.h>
#include <stdint.h>

// Problem constants (B=2, S=2048, D=1024, H=16, Dk=64)
#define BB 2
#define SS 2048
#define DD 1024
#define HH 16
#define DK 64
#define BH (BB*HH)

#define QSCALE (0.125f * 1.44269504088896340736f)
#define PADL 72   // k_lsum/k_wsum: 64-float rows + 8 pad (LDS.64 conflict-free)
#define PADP 36   // k_proj: 32-float rows + 4 pad

__device__ __forceinline__ uint32_t smaddr(const void* p) {
    return (uint32_t)__cvta_generic_to_shared(p);
}
__device__ __forceinline__ void cpa16(uint32_t dst, const void* src) {
    asm volatile("cp.async.cg.shared.global [%0], [%1], 16;" :: "r"(dst), "l"(src));
}
__device__ __forceinline__ void cpa16z(uint32_t dst, const void* src) {
    asm volatile("cp.async.cg.shared.global [%0], [%1], 16, 0;" :: "r"(dst), "l"(src));
}
#define CP_COMMIT() asm volatile("cp.async.commit_group;")
#define CP_WAIT0()  asm volatile("cp.async.wait_group 0;")
#define CP_WAIT1()  asm volatile("cp.async.wait_group 1;")

__device__ __forceinline__ uint32_t f2tf(float x) {
    uint32_t r; asm("cvt.rna.tf32.f32 %0, %1;" : "=r"(r) : "f"(x)); return r;
}
__device__ __forceinline__ uint32_t rna_bits(uint32_t u) {
    return f2tf(__uint_as_float(u));
}
// single-MUFU exponential / log (guaranteed fast path regardless of compile flags)
__device__ __forceinline__ float ex2(float x) {
    float r; asm("ex2.approx.f32 %0, %1;" : "=f"(r) : "f"(x)); return r;
}
__device__ __forceinline__ float lg2(float x) {
    float r; asm("lg2.approx.f32 %0, %1;" : "=f"(r) : "f"(x)); return r;
}
__device__ __forceinline__ void mma8(float* d, const uint32_t* a, uint32_t b0, uint32_t b1) {
    asm("mma.sync.aligned.m16n8k8.row.col.f32.tf32.tf32.f32 "
        "{%0,%1,%2,%3}, {%4,%5,%6,%7}, {%8,%9}, {%0,%1,%2,%3};"
        : "+f"(d[0]), "+f"(d[1]), "+f"(d[2]), "+f"(d[3])
        : "r"(a[0]), "r"(a[1]), "r"(a[2]), "r"(a[3]), "r"(b0), "r"(b1));
}

// ---- static device scratch ----
__device__ float g_Qh[BH*SS*DK];     // tf32-exact values
__device__ float g_Kh[BH*SS*DK];     // tf32-exact values
__device__ float g_WT[2*DD*DD];      // transposed + tf32-rounded Wq, Wk
__device__ float g_lb[BH*SS];
__device__ float g_w [BH*SS];
__device__ float g_ypart[16*BB*HH*DD];
__device__ float g_csp[64*DD];
__device__ float g_outp[64*DD];
__device__ int   g_qidx[BB*SS];
__device__ int   g_cnt [BB];
__device__ float g_cntf[BB];

// ---------------------------------------------------------------------------
// Kernel 0: deterministic mask compaction
// ---------------------------------------------------------------------------
__global__ void k_compact(const int* __restrict__ mask) {
    int b = blockIdx.x;
    int tid = threadIdx.x;
    __shared__ int cnts[256];
    __shared__ int offs[256];
    int base = tid * 8;
    int loc[8];
    int c = 0;
#pragma unroll
    for (int i = 0; i < 8; i++) { loc[i] = mask[b*SS + base + i]; c += (loc[i] != 0); }
    cnts[tid] = c;
    __syncthreads();
    if (tid == 0) {
        int run = 0;
        for (int i = 0; i < 256; i++) { offs[i] = run; run += cnts[i]; }
        g_cnt[b] = run;
        g_cntf[b] = (float)run;
    }
    __syncthreads();
    int o = offs[tid];
#pragma unroll
    for (int i = 0; i < 8; i++) {
        if (loc[i] != 0) { g_qidx[b*SS + o] = base + i; o++; }
    }
}

// ---------------------------------------------------------------------------
// Kernel 0b: transpose + tf32-round W -> g_WT[z]   grid (32,32,2)
// ---------------------------------------------------------------------------
__global__ void k_wtrans(const float* __restrict__ Wq, const float* __restrict__ Wk) {
    __shared__ float t[32][33];
    int sel = blockIdx.z;
    const float* Wsrc = sel ? Wk : Wq;
    float* Wdst = g_WT + (size_t)sel * DD * DD;
    int bx = blockIdx.x * 32, by = blockIdx.y * 32;
    int x = threadIdx.x & 31, y4 = (threadIdx.x >> 5) * 4;
#pragma unroll
    for (int i = 0; i < 4; i++)
        t[y4 + i][x] = Wsrc[(size_t)(by + y4 + i) * DD + bx + x];
    __syncthreads();
#pragma unroll
    for (int i = 0; i < 4; i++)
        Wdst[(size_t)(bx + y4 + i) * DD + by + x] =
            __uint_as_float(f2tf(t[x][y4 + i]));
}

// ---------------------------------------------------------------------------
// Kernel 1: both projection GEMMs in one launch (z = 0:Q, 1:K).   [R12 version]
// ---------------------------------------------------------------------------
__global__ __launch_bounds__(256) void k_proj(
    const float* __restrict__ Xq, const float* __restrict__ Xk,
    const float* __restrict__ bq, const float* __restrict__ bk)
{
    extern __shared__ __align__(16) uint32_t smu[];
    int which = blockIdx.z;
    const float* X    = which ? Xk : Xq;
    const float* Wt   = g_WT + (size_t)which * DD * DD;
    const float* bias = which ? bk : bq;
    float scale = which ? 1.0f : QSCALE;
    float* Out = which ? g_Kh : g_Qh;

    int tid = threadIdx.x;
    int w = tid >> 5, lane = tid & 31;
    int g = lane >> 2, t = lane & 3;
    int m0 = blockIdx.x * 128;
    int n0 = blockIdx.y * 128;

#define STAGE_P(s, k0)                                                           \
    {                                                                            \
        uint32_t* B_ = smu + (s) * 256 * PADP;                                   \
        _Pragma("unroll")                                                        \
        for (int i_ = 0; i_ < 8; i_++) {                                         \
            int idx_ = tid + 256 * i_;                                           \
            int row_ = idx_ >> 3, f4_ = idx_ & 7;                                \
            const float* src_ = (row_ < 128)                                     \
                ? (X  + (size_t)(m0 + row_) * DD + (k0) + f4_*4)                 \
                : (Wt + (size_t)(n0 + row_ - 128) * DD + (k0) + f4_*4);          \
            cpa16(smaddr(B_ + row_*PADP + f4_*4), src_);                         \
        }                                                                        \
    }

    float Dp[16][4];
#pragma unroll
    for (int nc = 0; nc < 16; nc++)
#pragma unroll
        for (int j = 0; j < 4; j++) Dp[nc][j] = 0.f;

    STAGE_P(0, 0); CP_COMMIT();
    for (int kt = 0; kt < 32; kt++) {
        if (kt < 31) { STAGE_P((kt + 1) & 1, (kt + 1) * 32); CP_COMMIT(); }
        if (kt < 31) { CP_WAIT1(); } else { CP_WAIT0(); }
        __syncthreads();
        uint32_t* Xs = smu + (kt & 1) * 256 * PADP;
        uint32_t* Ws = Xs + 128 * PADP;
        uint32_t A[4][4];
#pragma unroll
        for (int kc = 0; kc < 4; kc++) {
            int r0 = (w*16 + g)*PADP + t + 8*kc;
            A[kc][0] = rna_bits(Xs[r0]);
            A[kc][1] = rna_bits(Xs[r0 + 8*PADP]);
            A[kc][2] = rna_bits(Xs[r0 + 4]);
            A[kc][3] = rna_bits(Xs[r0 + 8*PADP + 4]);
        }
#pragma unroll
        for (int nc = 0; nc < 16; nc++) {
            int nb = (nc*8 + g)*PADP + t;
#pragma unroll
            for (int kc = 0; kc < 4; kc++)
                mma8(Dp[nc], A[kc], Ws[nb + 8*kc], Ws[nb + 8*kc + 4]);
        }
        __syncthreads();
    }
    int row0 = m0 + w*16 + g;
#pragma unroll
    for (int nc = 0; nc < 16; nc++) {
        int col = n0 + nc*8 + 2*t;
        float bx = bias[col], by = bias[col+1];
        int h = col >> 6, dd = col & 63;
        {
            int b_ = row0 >> 11, s = row0 & 2047;
            float2 o = make_float2(
                __uint_as_float(f2tf((Dp[nc][0] + bx) * scale)),
                __uint_as_float(f2tf((Dp[nc][1] + by) * scale)));
            *(float2*)(Out + (((size_t)(b_*HH + h) * SS + s) << 6) + dd) = o;
        }
        {
            int row1 = row0 + 8;
            int b_ = row1 >> 11, s = row1 & 2047;
            float2 o = make_float2(
                __uint_as_float(f2tf((Dp[nc][2] + bx) * scale)),
                __uint_as_float(f2tf((Dp[nc][3] + by) * scale)));
            *(float2*)(Out + (((size_t)(b_*HH + h) * SS + s) << 6) + dd) = o;
        }
    }
#undef STAGE_P
}

// ---------------------------------------------------------------------------
// Kernel 2 (pass A): lb[q] via tf32 mma; LDS.64 frags; ex2.approx.
// ---------------------------------------------------------------------------
__global__ __launch_bounds__(256) void k_lsum() {
    extern __shared__ __align__(16) uint32_t smu[];
    uint32_t* Qs = smu;

    int qt = blockIdx.x, bh = blockIdx.y;
    int b = bh >> 4;
    int cnt = g_cnt[b];
    if (qt * 128 >= cnt) return;
    int tid = threadIdx.x;
    int w = tid >> 5, lane = tid & 31;
    int g = lane >> 2, t = lane & 3;
    const float* Qbase = g_Qh + (size_t)bh * SS * 64;
    const float* Kbase = g_Kh + (size_t)bh * SS * 64;

#pragma unroll
    for (int i = 0; i < 8; i++) {
        int idx = tid + 256 * i;
        int row = idx >> 4, d4 = idx & 15;
        int ci = qt*128 + row;
        uint32_t dst = smaddr(Qs + row*PADL + d4*4);
        if (ci < cnt) {
            int s = g_qidx[b*SS + ci];
            cpa16(dst, Qbase + ((size_t)s << 6) + d4*4);
        } else {
            cpa16z(dst, Qbase);
        }
    }
    CP_COMMIT();

#define STAGE_K(kt, s)                                                           \
    {                                                                            \
        uint32_t* Kb_ = smu + 128*PADL + (s) * 128 * PADL;                       \
        _Pragma("unroll")                                                        \
        for (int i_ = 0; i_ < 8; i_++) {                                         \
            int idx_ = tid + 256 * i_;                                           \
            int row_ = idx_ >> 4, d4_ = idx_ & 15;                               \
            cpa16(smaddr(Kb_ + row_*PADL + d4_*4),                               \
                  Kbase + ((size_t)((kt)*128 + row_) << 6) + d4_*4);             \
        }                                                                        \
    }

    STAGE_K(0, 0); CP_COMMIT();
    CP_WAIT1();
    __syncthreads();
    uint32_t A[8][4];
#pragma unroll
    for (int kc = 0; kc < 8; kc++) {
        int r0 = (w*16 + g)*PADL + 8*kc + 2*t;
        uint2 pa0 = *(const uint2*)(Qs + r0);
        uint2 pa1 = *(const uint2*)(Qs + r0 + 8*PADL);
        A[kc][0] = pa0.x; A[kc][2] = pa0.y;
        A[kc][1] = pa1.x; A[kc][3] = pa1.y;
    }
    float rs_lo = 0.f, rs_hi = 0.f;
    for (int kt = 0; kt < 16; kt++) {
        if (kt < 15) { STAGE_K(kt + 1, (kt + 1) & 1); CP_COMMIT(); }
        if (kt < 15) { CP_WAIT1(); } else { CP_WAIT0(); }
        __syncthreads();
        uint32_t* Ks = smu + 128*PADL + (kt & 1) * 128 * PADL;
#pragma unroll 4
        for (int nc = 0; nc < 16; nc++) {
            float c[4] = {0.f, 0.f, 0.f, 0.f};
            int nb = (nc*8 + g)*PADL + 2*t;
#pragma unroll
            for (int kc = 0; kc < 8; kc++) {
                uint2 pb = *(const uint2*)(Ks + nb + 8*kc);
                mma8(c, A[kc], pb.x, pb.y);
            }
            rs_lo += ex2(c[0]) + ex2(c[1]);
            rs_hi += ex2(c[2]) + ex2(c[3]);
        }
        __syncthreads();
    }
    rs_lo += __shfl_xor_sync(0xffffffffu, rs_lo, 1);
    rs_lo += __shfl_xor_sync(0xffffffffu, rs_lo, 2);
    rs_hi += __shfl_xor_sync(0xffffffffu, rs_hi, 1);
    rs_hi += __shfl_xor_sync(0xffffffffu, rs_hi, 2);
    if (t == 0) {
        int ci = qt*128 + w*16 + g;
        if (ci < cnt)     g_lb[bh*SS + ci]     = lg2(rs_lo);
        if (ci + 8 < cnt) g_lb[bh*SS + ci + 8] = lg2(rs_hi);
    }
#undef STAGE_K
}

// ---------------------------------------------------------------------------
// Kernel 3 (pass B): w[k] via tf32 mma, TRANSPOSED orientation; ex2.approx.
// dyn smem 111104 B (2 CTA/SM). grid (16, 32).
// ---------------------------------------------------------------------------
__global__ __launch_bounds__(256) void k_wsum() {
    extern __shared__ __align__(16) uint32_t smu[];
    uint32_t* Ks = smu;                         // [128][PADL] keys (persistent)
    float* lbs = (float*)(smu + 3*128*PADL);    // [128]

    int kt = blockIdx.x, bh = blockIdx.y;
    int b = bh >> 4;
    int cnt = g_cnt[b];
    int tid = threadIdx.x;
    int w = tid >> 5, lane = tid & 31;
    int g = lane >> 2, t = lane & 3;
    const float* Qbase = g_Qh + (size_t)bh * SS * 64;
    const float* Kbase = g_Kh + (size_t)bh * SS * 64;
    const float* lbp = g_lb + (size_t)bh * SS;

    // stage persistent 128-key K tile (group 0)
#pragma unroll
    for (int i = 0; i < 8; i++) {
        int idx = tid + 256 * i;
        int row = idx >> 4, d4 = idx & 15;
        cpa16(smaddr(Ks + row*PADL + d4*4),
              Kbase + ((size_t)(kt*128 + row) << 6) + d4*4);
    }
    CP_COMMIT();

#define STAGE_QT(qt, s)                                                          \
    {                                                                            \
        uint32_t* Qb_ = smu + 128*PADL + (s) * 128 * PADL;                       \
        _Pragma("unroll")                                                        \
        for (int i_ = 0; i_ < 8; i_++) {                                         \
            int idx_ = tid + 256 * i_;                                           \
            int row_ = idx_ >> 4, d4_ = idx_ & 15;                               \
            int ci_ = (qt)*128 + row_;                                           \
            uint32_t dst_ = smaddr(Qb_ + row_*PADL + d4_*4);                     \
            if (ci_ < cnt) {                                                     \
                int s_ = g_qidx[b*SS + ci_];                                     \
                cpa16(dst_, Qbase + ((size_t)s_ << 6) + d4_*4);                  \
            } else {                                                             \
                cpa16z(dst_, Qbase);                                             \
            }                                                                    \
        }                                                                        \
    }

    int nqt = (cnt + 127) >> 7;
    if (nqt > 0) { STAGE_QT(0, 0); CP_COMMIT(); }

    if (nqt > 0) { CP_WAIT1(); } else { CP_WAIT0(); }
    __syncthreads();
    uint32_t A[8][4];
#pragma unroll
    for (int kc = 0; kc < 8; kc++) {
        int r0 = (w*16 + g)*PADL + 8*kc + 2*t;
        uint2 pa0 = *(const uint2*)(Ks + r0);
        uint2 pa1 = *(const uint2*)(Ks + r0 + 8*PADL);
        A[kc][0] = pa0.x; A[kc][2] = pa0.y;
        A[kc][1] = pa1.x; A[kc][3] = pa1.y;
    }

    float wlo = 0.f, whi = 0.f;
    for (int qt = 0; qt < nqt; qt++) {
        if (qt + 1 < nqt) { STAGE_QT(qt + 1, (qt + 1) & 1); CP_COMMIT(); }
        if (tid < 128) {
            int ci = qt*128 + tid;
            lbs[tid] = (ci < cnt) ? lbp[ci] : 1e9f;
        }
        if (qt + 1 < nqt) { CP_WAIT1(); } else { CP_WAIT0(); }
        __syncthreads();
        uint32_t* Qs = smu + 128*PADL + (qt & 1) * 128 * PADL;
#pragma unroll 4
        for (int nc = 0; nc < 16; nc++) {
            float c[4] = {0.f, 0.f, 0.f, 0.f};
            int nb = (nc*8 + g)*PADL + 2*t;
#pragma unroll
            for (int kc = 0; kc < 8; kc++) {
                uint2 pb = *(const uint2*)(Qs + nb + 8*kc);
                mma8(c, A[kc], pb.x, pb.y);
            }
            float lb0 = lbs[nc*8 + 2*t];
            float lb1 = lbs[nc*8 + 2*t + 1];
            wlo += ex2(c[0] - lb0) + ex2(c[1] - lb1);
            whi += ex2(c[2] - lb0) + ex2(c[3] - lb1);
        }
        __syncthreads();
    }
    // reduce over the 4 t-lanes
    wlo += __shfl_xor_sync(0xffffffffu, wlo, 1);
    wlo += __shfl_xor_sync(0xffffffffu, wlo, 2);
    whi += __shfl_xor_sync(0xffffffffu, whi, 1);
    whi += __shfl_xor_sync(0xffffffffu, whi, 2);
    if (t == 0) {
        int key = kt*128 + w*16 + g;
        g_w[bh*SS + key]     = wlo;
        g_w[bh*SS + key + 8] = whi;
    }
#undef STAGE_QT
}

// ---------------------------------------------------------------------------
// Kernel 4: y-partials (unchanged)
// ---------------------------------------------------------------------------
__global__ __launch_bounds__(256) void k_ypart(const float* __restrict__ v) {
    int id = blockIdx.x;
    int kt = id & 15;
    int jt = (id >> 4) & 3;
    int b  = id >> 6;
    __shared__ float wsh[16][128];
    int tid = threadIdx.x;
#pragma unroll
    for (int i = 0; i < 8; i++) {
        int idx = tid + 256 * i;
        int h = idx >> 7, kk = idx & 127;
        wsh[h][kk] = g_w[(b*HH + h) * SS + kt*128 + kk];
    }
    __syncthreads();
    int j = jt * 256 + tid;
    float acc[16];
#pragma unroll
    for (int h = 0; h < 16; h++) acc[h] = 0.f;
    const float* vb = v + ((size_t)b * SS + kt*128) * 1024 + j;
    for (int kk = 0; kk < 128; kk++) {
        float vv = vb[(size_t)kk * 1024];
#pragma unroll
        for (int h = 0; h < 16; h++) acc[h] += wsh[h][kk] * vv;
    }
#pragma unroll
    for (int h = 0; h < 16; h++)
        g_ypart[((size_t)(kt*BB + b) * HH + h) * DD + j] = acc[h];
}

// ---------------------------------------------------------------------------
// Kernel 5 (FUSED yred + cs_part)
// ---------------------------------------------------------------------------
__global__ __launch_bounds__(256) void k_cs_part(const float* __restrict__ Wv) {
    __shared__ float ys[16][32];
    int bid = blockIdx.x;
    int b = bid >> 5, jc = bid & 31;
    int tid = threadIdx.x;

#pragma unroll
    for (int r = 0; r < 2; r++) {
        int idx = tid + 256 * r;
        int h = idx >> 5, jl = idx & 31;
        int j = jc*32 + jl;
        float s = 0.f;
#pragma unroll
        for (int kt = 0; kt < 16; kt++)
            s += g_ypart[((size_t)(kt*BB + b) * HH + h) * DD + j];
        ys[h][jl] = s;
    }
    __syncthreads();

    int c0 = tid * 4;
    int h = tid >> 4;
    float4 s = make_float4(0.f, 0.f, 0.f, 0.f);
#pragma unroll 8
    for (int jl = 0; jl < 32; jl++) {
        float yv = ys[h][jl];
        float4 w4 = *(const float4*)(Wv + (size_t)(jc*32 + jl) * 1024 + c0);
        s.x += yv * w4.x; s.y += yv * w4.y; s.z += yv * w4.z; s.w += yv * w4.w;
    }
    *(float4*)(g_csp + (size_t)bid * DD + c0) = s;
}

// ---------------------------------------------------------------------------
// Kernel 6 (FUSED cs_red + out_part)
// ---------------------------------------------------------------------------
__global__ __launch_bounds__(256) void k_out_part(
    const float* __restrict__ Wo, const float* __restrict__ bv)
{
    __shared__ float css[32];
    int bid = blockIdx.x;
    int b = bid >> 5, jc = bid & 31;
    int tid = threadIdx.x;

    if (tid < 32) {
        int c = jc*32 + tid;
        float s = 0.f;
#pragma unroll
        for (int p = 0; p < 32; p++) s += g_csp[(size_t)(b*32 + p) * DD + c];
        css[tid] = s + g_cntf[b] * bv[c];
    }
    __syncthreads();

    int d0 = tid * 4;
    float4 s = make_float4(0.f, 0.f, 0.f, 0.f);
#pragma unroll 8
    for (int cl = 0; cl < 32; cl++) {
        float cv = css[cl];
        float4 w4 = *(const float4*)(Wo + (size_t)(jc*32 + cl) * 1024 + d0);
        s.x += cv * w4.x; s.y += cv * w4.y; s.z += cv * w4.z; s.w += cv * w4.w;
    }
    *(float4*)(g_outp + (size_t)bid * DD + d0) = s;
}

// ---------------------------------------------------------------------------
// Kernel 7: final reduce
// ---------------------------------------------------------------------------
__global__ void k_out_red(const float* __restrict__ bo, float* __restrict__ out) {
    int idx = blockIdx.x * 256 + threadIdx.x;
    int b = idx >> 10, d = idx & 1023;
    float s = 0.f;
#pragma unroll
    for (int jc = 0; jc < 32; jc++) s += g_outp[(size_t)(b*32 + jc) * DD + d];
    out[idx] = s + g_cntf[b] * bo[d];
}

// ---------------------------------------------------------------------------
extern "C" void kernel_launch(void* const* d_in, const int* in_sizes, int n_in,
                              void* d_out, int out_size) {
    const float* q    = (const float*)d_in[0];
    const float* k    = (const float*)d_in[1];
    const float* v    = (const float*)d_in[2];
    const int*   mask = (const int*)  d_in[3];
    const float* Wq   = (const float*)d_in[4];
    const float* bq   = (const float*)d_in[5];
    const float* Wk   = (const float*)d_in[6];
    const float* bk   = (const float*)d_in[7];
    const float* Wv   = (const float*)d_in[8];
    const float* bv   = (const float*)d_in[9];
    const float* Wo   = (const float*)d_in[10];
    const float* bo   = (const float*)d_in[11];
    float* out = (float*)d_out;

    const int SM_PROJ = 2 * 256 * PADP * 4;             // 73728  (3 CTA/SM)
    const int SM_LSUM = 3 * 128 * PADL * 4;             // 110592 (2 CTA/SM)
    const int SM_WSUM = 3 * 128 * PADL * 4 + 512;       // 111104 (2 CTA/SM)

    cudaFuncSetAttribute(k_proj, cudaFuncAttributeMaxDynamicSharedMemorySize, SM_PROJ);
    cudaFuncSetAttribute(k_lsum, cudaFuncAttributeMaxDynamicSharedMemorySize, SM_LSUM);
    cudaFuncSetAttribute(k_wsum, cudaFuncAttributeMaxDynamicSharedMemorySize, SM_WSUM);

    k_compact<<<BB, 256>>>(mask);
    k_wtrans<<<dim3(32, 32, 2), 256>>>(Wq, Wk);
    k_proj<<<dim3(32, 8, 2), 256, SM_PROJ>>>(q, k, bq, bk);
    k_lsum<<<dim3(16, 32), 256, SM_LSUM>>>();
    k_wsum<<<dim3(16, 32), 256, SM_WSUM>>>();
    k_ypart<<<128, 256>>>(v);
    k_cs_part<<<64, 256>>>(Wv);
    k_out_part<<<64, 256>>>(Wo, bv);
    k_out_red<<<8, 256>>>(bo, out);
}